// round 8
// baseline (speedup 1.0000x reference)
#include <cuda_runtime.h>
#include <cuda_bf16.h>
#include <cstdint>

#define B_ 128
#define T_ 2048
#define TT 64
#define NTILES (T_ / TT)
#define NTHR 256
#define QSTR 132

// smem word offsets (per-CTA total ~101.3 KB -> 2 CTAs/SM)
#define WSH_OFF 0              // 16384 words: W half (128 douts x 256 k bf16), XOR swizzle
#define Q_OFF   16384          // 8448 words: Q tile (64 tok x 256 k bf16, QSTR stride)
#define WG_OFF  24832          // 256 words: float2 {w[d], gpr[d]} for local douts
#define E_OFF   25088          // 64 words
#define AP_OFF  25152          // 256 words: alpha_part[64][4]
#define ZB_OFF  25408          // 512 words: zbuf[4][128] (ph[512] in prologue)
#define RED_OFF 25920          // 8 words
#define SMEM_WORDS 25928

__device__ float g_part[B_ * 2 * NTILES * TT];   // 2 MB scratch (allowed: __device__ global)
__device__ int   g_flag[B_ * 2 * NTILES];        // zero-initialized static storage

__device__ __forceinline__ float fast_tanh(float x) {
    float y;
    asm("tanh.approx.f32 %0, %1;" : "=f"(y) : "f"(x));
    return y;
}
__device__ __forceinline__ void st_release(int* p, int v) {
    asm volatile("st.release.gpu.global.b32 [%0], %1;" :: "l"(p), "r"(v) : "memory");
}
__device__ __forceinline__ int ld_acquire(const int* p) {
    int v;
    asm volatile("ld.acquire.gpu.global.b32 %0, [%1];" : "=r"(v) : "l"(p) : "memory");
    return v;
}

__global__ __launch_bounds__(NTHR, 2)
void kFused(const float* __restrict__ input_q,
            const float* __restrict__ W_q,
            const float* __restrict__ wvec,
            const float* __restrict__ match_b,
            const int* __restrict__ mask_q,
            const float* __restrict__ input_p,
            const float* __restrict__ h_tm1,
            const float* __restrict__ W_p_r,
            const float* __restrict__ b_p_r,
            const float* __restrict__ b_q,
            float* __restrict__ out) {
    extern __shared__ uint32_t sh[];
    uint32_t* Wsh = sh + WSH_OFF;
    uint32_t* Qsh = sh + Q_OFF;
    float2* wg_sh = reinterpret_cast<float2*>(sh + WG_OFF);
    float*  e_sh  = reinterpret_cast<float*>(sh + E_OFF);
    float*  ap_sh = reinterpret_cast<float*>(sh + AP_OFF);
    float*  zbuf  = reinterpret_cast<float*>(sh + ZB_OFF);
    float*  red   = reinterpret_cast<float*>(sh + RED_OFF);

    int bh   = blockIdx.x;
    int b    = bh >> 1;
    int half = bh & 1;
    int tid  = threadIdx.x;
    int lane = tid & 31, wid = tid >> 5;

    // ================= Prologue =================
    float* ph = zbuf;                    // [512] = [input_p | h_tm1]
    ph[tid]       = input_p[b * 256 + tid];
    ph[256 + tid] = h_tm1[b * 256 + tid];
    __syncthreads();

    // gpr for local douts: 8 warps x 16 rows
    for (int r = 0; r < 16; ++r) {
        int dl = wid * 16 + r;
        int dg = half * 128 + dl;
        const float4* row = reinterpret_cast<const float4*>(W_p_r + (size_t)dg * 512);
        const float4* p4  = reinterpret_cast<const float4*>(ph);
        float acc = 0.f;
#pragma unroll
        for (int i = 0; i < 4; ++i) {
            float4 wv = row[i * 32 + lane];
            float4 pv = p4[i * 32 + lane];
            acc += wv.x * pv.x + wv.y * pv.y + wv.z * pv.z + wv.w * pv.w;
        }
#pragma unroll
        for (int o = 16; o; o >>= 1) acc += __shfl_xor_sync(0xffffffffu, acc, o);
        if (lane == 0) wg_sh[dl] = make_float2(wvec[dg], acc + b_p_r[dg] + b_q[dg]);
    }

    // W half (fp32) -> bf16 smem, XOR swizzle
    for (int i = tid; i < 128 * 128; i += NTHR) {
        int nl = i >> 7, kw = i & 127;
        float2 f = reinterpret_cast<const float2*>(W_q)[(half * 128 + nl) * 128 + kw];
        __nv_bfloat162 h = __floats2bfloat162_rn(f.x, f.y);
        int phys = (kw >> 2) ^ (nl & 7);
        Wsh[nl * 128 + phys * 4 + (kw & 3)] = *reinterpret_cast<uint32_t*>(&h);
    }

    const float   mb  = match_b[0];
    const float4* qb4 = reinterpret_cast<const float4*>(input_q + (size_t)b * T_ * 256);
    const int*    mqb = mask_q + (size_t)b * T_;

    // Q tile 0
#pragma unroll
    for (int j = 0; j < 16; ++j) {
        int idx = tid + j * NTHR;
        float4 f = qb4[idx];
        int row = idx >> 6, c4 = idx & 63;
        __nv_bfloat162 h0 = __floats2bfloat162_rn(f.x, f.y);
        __nv_bfloat162 h1 = __floats2bfloat162_rn(f.z, f.w);
        Qsh[row * QSTR + c4 * 2]     = *reinterpret_cast<uint32_t*>(&h0);
        Qsh[row * QSTR + c4 * 2 + 1] = *reinterpret_cast<uint32_t*>(&h1);
    }
    __syncthreads();

    // ================= Main loop =================
    int warp_m = wid & 1;     // 2 warps over 64 tokens
    int warp_n = wid >> 1;    // 4 warps over 128 local douts
    int zw = tid & 63;        // d-pair word within half
    int zq = tid >> 6;        // t-quarter (16 tokens)
    int zword = half * 64 + zw;

    float Sth = 0.f, Mth = -1e30f;   // warp 0 lanes (2 rows each)
    float z0 = 0.f, z1 = 0.f;

    for (int it = 0; it < NTILES; ++it) {
        int m0 = 0, m1 = 0;
        if (wid == 0) { m0 = mqb[it * TT + lane]; m1 = mqb[it * TT + 32 + lane]; }

        bool has_next = (it + 1 < NTILES);
        const float4* src = qb4 + (size_t)(it + 1) * TT * 64;

        // ---- MMA: C[64 x 128] = Qtile @ Whalf^T, warp tile m32 x n32
        float c[8][4];
#pragma unroll
        for (int q = 0; q < 8; ++q) { c[q][0] = c[q][1] = c[q][2] = c[q][3] = 0.f; }

#pragma unroll 4
        for (int kc = 0; kc < 16; ++kc) {
            uint32_t a[2][4];
#pragma unroll
            for (int mt = 0; mt < 2; ++mt) {
                int arow = warp_m * 32 + mt * 16 + (lane & 15);
                int acol = kc * 8 + ((lane & 16) ? 4 : 0);
                uint32_t aaddr = (uint32_t)__cvta_generic_to_shared(&Qsh[arow * QSTR + acol]);
                asm volatile("ldmatrix.sync.aligned.m8n8.x4.shared.b16 {%0,%1,%2,%3}, [%4];"
                             : "=r"(a[mt][0]), "=r"(a[mt][1]), "=r"(a[mt][2]), "=r"(a[mt][3])
                             : "r"(aaddr));
            }
#pragma unroll
            for (int np = 0; np < 2; ++np) {
                int row   = warp_n * 32 + np * 16 + (lane & 7) + ((lane & 16) ? 8 : 0);
                int physB = (kc * 2 + ((lane & 8) ? 1 : 0)) ^ (row & 7);
                uint32_t baddr = (uint32_t)__cvta_generic_to_shared(&Wsh[row * 128 + physB * 4]);
                uint32_t b0, b1, b2, b3;
                asm volatile("ldmatrix.sync.aligned.m8n8.x4.shared.b16 {%0,%1,%2,%3}, [%4];"
                             : "=r"(b0), "=r"(b1), "=r"(b2), "=r"(b3) : "r"(baddr));
#pragma unroll
                for (int mt = 0; mt < 2; ++mt) {
                    float* c0 = c[mt * 4 + np * 2];
                    float* c1 = c[mt * 4 + np * 2 + 1];
                    asm volatile(
                        "mma.sync.aligned.m16n8k16.row.col.f32.bf16.bf16.f32 "
                        "{%0,%1,%2,%3}, {%4,%5,%6,%7}, {%8,%9}, {%0,%1,%2,%3};"
                        : "+f"(c0[0]), "+f"(c0[1]), "+f"(c0[2]), "+f"(c0[3])
                        : "r"(a[mt][0]), "r"(a[mt][1]), "r"(a[mt][2]), "r"(a[mt][3]),
                          "r"(b0), "r"(b1));
                    asm volatile(
                        "mma.sync.aligned.m16n8k16.row.col.f32.bf16.bf16.f32 "
                        "{%0,%1,%2,%3}, {%4,%5,%6,%7}, {%8,%9}, {%0,%1,%2,%3};"
                        : "+f"(c1[0]), "+f"(c1[1]), "+f"(c1[2]), "+f"(c1[3])
                        : "r"(a[mt][0]), "r"(a[mt][1]), "r"(a[mt][2]), "r"(a[mt][3]),
                          "r"(b2), "r"(b3));
                }
            }
        }

        // ---- prefetch next tile, convert to bf16 in regs (latency under epilogue)
        uint2 stg[16];
        if (has_next) {
#pragma unroll
            for (int j = 0; j < 16; ++j) {
                float4 f = src[tid + j * NTHR];
                __nv_bfloat162 h0 = __floats2bfloat162_rn(f.x, f.y);
                __nv_bfloat162 h1 = __floats2bfloat162_rn(f.z, f.w);
                stg[j] = make_uint2(*reinterpret_cast<uint32_t*>(&h0),
                                    *reinterpret_cast<uint32_t*>(&h1));
            }
        }

        // ---- epilogue: tanh + dot(w), quad reduce, disjoint partials
#pragma unroll
        for (int mt = 0; mt < 2; ++mt) {
            float p0 = 0.f, p1 = 0.f;
#pragma unroll
            for (int np = 0; np < 2; ++np) {
#pragma unroll
                for (int j = 0; j < 2; ++j) {
                    int n = warp_n * 32 + np * 16 + j * 8 + (lane & 3) * 2;
                    float4 wg = *reinterpret_cast<const float4*>(&wg_sh[n]);
                    float* cc = c[mt * 4 + np * 2 + j];
                    p0 += wg.x * fast_tanh(cc[0] + wg.y) + wg.z * fast_tanh(cc[1] + wg.w);
                    p1 += wg.x * fast_tanh(cc[2] + wg.y) + wg.z * fast_tanh(cc[3] + wg.w);
                }
            }
            p0 += __shfl_xor_sync(0xffffffffu, p0, 1);
            p0 += __shfl_xor_sync(0xffffffffu, p0, 2);
            p1 += __shfl_xor_sync(0xffffffffu, p1, 1);
            p1 += __shfl_xor_sync(0xffffffffu, p1, 2);
            if ((lane & 3) == 0) {
                int row0 = warp_m * 32 + mt * 16 + (lane >> 2);
                ap_sh[row0 * 4 + warp_n]       = p0;
                ap_sh[(row0 + 8) * 4 + warp_n] = p1;
            }
        }
        __syncthreads();   // S1

        // ---- warp 0: half-sum exchange via global + exp
        if (wid == 0) {
            float4 a0 = *reinterpret_cast<float4*>(&ap_sh[lane * 4]);
            float4 a1 = *reinterpret_cast<float4*>(&ap_sh[(lane + 32) * 4]);
            float v0 = (a0.x + a0.y) + (a0.z + a0.w);
            float v1 = (a1.x + a1.y) + (a1.z + a1.w);
            size_t mybase = ((size_t)(b * 2 + half) * NTILES + it) * TT;
            g_part[mybase + lane]      = v0;
            g_part[mybase + 32 + lane] = v1;
            __syncwarp();
            __threadfence();
            int* myflag = &g_flag[(b * 2 + half) * NTILES + it];
            if (lane == 0) st_release(myflag, 1);
            const int* pflag = &g_flag[(b * 2 + (1 - half)) * NTILES + it];
            if (lane == 0) { while (ld_acquire(pflag) == 0) { } }
            __syncwarp();
            size_t pbase = ((size_t)(b * 2 + (1 - half)) * NTILES + it) * TT;
            float t0 = v0 + __ldcg(&g_part[pbase + lane]) + mb;
            float t1 = v1 + __ldcg(&g_part[pbase + 32 + lane]) + mb;
            float m0f = (float)m0, m1f = (float)m1;
            float x0 = fminf(fmaxf(t0, -15.f), 15.f) * m0f;
            float x1 = fminf(fmaxf(t1, -15.f), 15.f) * m1f;
            float e0 = __expf(x0 - 15.f) * m0f;
            float e1 = __expf(x1 - 15.f) * m1f;
            e_sh[lane]      = e0;
            e_sh[lane + 32] = e1;
            Sth += e0 + e1;
            Mth = fmaxf(Mth, fmaxf(x0, x1));
        }
        __syncthreads();   // S2: e_sh ready

        // ---- z update (local douts): thread owns d-pair zw, t-quarter zq
        {
            float a0 = 0.f, a1 = 0.f;
            int tb = zq * 16;
#pragma unroll
            for (int k = 0; k < 16; ++k) {
                int t = tb + k;
                uint32_t qw = Qsh[t * QSTR + zword];
                __nv_bfloat162 h2 = *reinterpret_cast<__nv_bfloat162*>(&qw);
                float e = e_sh[t];
                a0 += e * __bfloat162float(__low2bfloat16(h2));
                a1 += e * __bfloat162float(__high2bfloat16(h2));
            }
            z0 += a0;
            z1 += a1;
        }
        __syncthreads();   // S3: Q reads done

        // ---- store next tile
        if (has_next) {
#pragma unroll
            for (int j = 0; j < 16; ++j) {
                int idx = tid + j * NTHR;
                int row = idx >> 6, c4 = idx & 63;
                *reinterpret_cast<uint2*>(&Qsh[row * QSTR + c4 * 2]) = stg[j];
            }
        }
        __syncthreads();   // S4
    }

    // ================= Final =================
    if (wid == 0) {
        float s = Sth, m = Mth;
#pragma unroll
        for (int o = 16; o; o >>= 1) {
            s += __shfl_xor_sync(0xffffffffu, s, o);
            m = fmaxf(m, __shfl_xor_sync(0xffffffffu, m, o));
        }
        if (lane == 0) { red[0] = s; red[1] = m; }
    }
    zbuf[zq * 128 + zw * 2]     = z0;
    zbuf[zq * 128 + zw * 2 + 1] = z1;
    __syncthreads();

    float denom = red[0] + 1e-6f * __expf(red[1] - 15.f);
    if (half == 0) out[b * 512 + tid] = input_p[b * 256 + tid];
    if (tid < 128) {
        float zt = (zbuf[tid] + zbuf[128 + tid]) + (zbuf[256 + tid] + zbuf[384 + tid]);
        out[b * 512 + 256 + half * 128 + tid] = zt / denom;
    }
}

extern "C" void kernel_launch(void* const* d_in, const int* in_sizes, int n_in,
                              void* d_out, int out_size) {
    const float* input_p = (const float*)d_in[0];
    const float* input_q = (const float*)d_in[2];
    const int*   mask_q  = (const int*)d_in[3];
    const float* h_tm1   = (const float*)d_in[4];
    const float* W_p_r   = (const float*)d_in[5];
    const float* b_p_r   = (const float*)d_in[6];
    const float* W_q     = (const float*)d_in[7];
    const float* b_q     = (const float*)d_in[8];
    const float* wv      = (const float*)d_in[9];
    const float* match_b = (const float*)d_in[10];
    float* out = (float*)d_out;

    size_t smemF = (size_t)SMEM_WORDS * 4;
    cudaFuncSetAttribute(kFused, cudaFuncAttributeMaxDynamicSharedMemorySize, (int)smemF);
    kFused<<<B_ * 2, NTHR, smemF>>>(input_q, W_q, wv, match_b, mask_q,
                                    input_p, h_tm1, W_p_r, b_p_r, b_q, out);
}

// round 9
// speedup vs baseline: 1.1954x; 1.1954x over previous
#include <cuda_runtime.h>
#include <cuda_bf16.h>
#include <cstdint>

#define B_ 128
#define T_ 2048
#define TT 64
#define NTILES 32
#define QSTR 132
#define NTHR 512

// smem word offsets
#define WSH_OFF 0                          // 32768: W bf16 swizzled
#define Q0_OFF  32768                      // 8448
#define Q1_OFF  (Q0_OFF + TT * QSTR)       // 41216
#define WG_OFF  (Q1_OFF + TT * QSTR)       // 49664: float2 {w,gpr} x256
#define E_OFF   (WG_OFF + 512)             // 50176: e[64]
#define AP_OFF  (E_OFF + 64)               // 50240: ap[64][8]
#define RED_OFF (AP_OFF + 512)             // 50752: 8
#define ZB_OFF  (RED_OFF + 8)              // 50760: zbuf[4][256] (ph[512] in prologue)
#define SMEM_WORDS (ZB_OFF + 1024)

__device__ __forceinline__ float fast_tanh(float x) {
    float y;
    asm("tanh.approx.f32 %0, %1;" : "=f"(y) : "f"(x));
    return y;
}

__global__ __launch_bounds__(NTHR, 1)
void kFused(const float* __restrict__ input_q,
            const float* __restrict__ W_q,
            const float* __restrict__ wvec,
            const float* __restrict__ match_b,
            const int* __restrict__ mask_q,
            const float* __restrict__ input_p,
            const float* __restrict__ h_tm1,
            const float* __restrict__ W_p_r,
            const float* __restrict__ b_p_r,
            const float* __restrict__ b_q,
            float* __restrict__ out) {
    extern __shared__ uint32_t sh[];
    uint32_t* Wsh = sh + WSH_OFF;
    float2* wg_sh = reinterpret_cast<float2*>(sh + WG_OFF);
    float*  e_sh  = reinterpret_cast<float*>(sh + E_OFF);
    float*  ap_sh = reinterpret_cast<float*>(sh + AP_OFF);
    float*  red   = reinterpret_cast<float*>(sh + RED_OFF);
    float*  zbuf  = reinterpret_cast<float*>(sh + ZB_OFF);

    int b    = blockIdx.x;
    int tid  = threadIdx.x;
    int lane = tid & 31, wid = tid >> 5;

    // ================= Prologue =================
    float* ph = zbuf;                       // [512] = [input_p | h_tm1]
    if (tid < 256) ph[tid]       = input_p[b * 256 + tid];
    else           ph[tid]       = h_tm1[b * 256 + (tid - 256)];
    __syncthreads();

    // gpr: 16 warps x 16 rows
    for (int r = 0; r < 16; ++r) {
        int d = wid * 16 + r;
        const float4* row = reinterpret_cast<const float4*>(W_p_r + (size_t)d * 512);
        const float4* p4  = reinterpret_cast<const float4*>(ph);
        float acc = 0.f;
#pragma unroll
        for (int i = 0; i < 4; ++i) {
            float4 wv = row[i * 32 + lane];
            float4 pv = p4[i * 32 + lane];
            acc += wv.x * pv.x + wv.y * pv.y + wv.z * pv.z + wv.w * pv.w;
        }
#pragma unroll
        for (int o = 16; o; o >>= 1) acc += __shfl_xor_sync(0xffffffffu, acc, o);
        if (lane == 0) wg_sh[d] = make_float2(wvec[d], acc + b_p_r[d] + b_q[d]);
    }

    // W_q -> bf16 smem, XOR swizzle
    for (int i = tid; i < 256 * 128; i += NTHR) {
        int n = i >> 7, kw = i & 127;
        float2 f = reinterpret_cast<const float2*>(W_q)[n * 128 + kw];
        __nv_bfloat162 h = __floats2bfloat162_rn(f.x, f.y);
        int phys = (kw >> 2) ^ (n & 7);
        Wsh[n * 128 + phys * 4 + (kw & 3)] = *reinterpret_cast<uint32_t*>(&h);
    }

    const float   mb  = match_b[0];
    const float4* qb4 = reinterpret_cast<const float4*>(input_q + (size_t)b * T_ * 256);
    const int*    mqb = mask_q + (size_t)b * T_;

    // Q tile 0 -> Qsh0
#pragma unroll
    for (int j = 0; j < 8; ++j) {
        int idx = tid + j * NTHR;
        float4 f = qb4[idx];
        int row = idx >> 6, c4 = idx & 63;
        __nv_bfloat162 h0 = __floats2bfloat162_rn(f.x, f.y);
        __nv_bfloat162 h1 = __floats2bfloat162_rn(f.z, f.w);
        sh[Q0_OFF + row * QSTR + c4 * 2]     = *reinterpret_cast<uint32_t*>(&h0);
        sh[Q0_OFF + row * QSTR + c4 * 2 + 1] = *reinterpret_cast<uint32_t*>(&h1);
    }
    __syncthreads();

    // ================= Main loop =================
    int warp_m = wid & 1;       // 2 warps over 64 tokens (m32 each)
    int warp_n = wid >> 1;      // 8 warps over 256 douts (n32 each)
    int zword = tid & 127;      // d-pair word
    int zq    = tid >> 7;       // t-quarter (16 tokens)

    float Sth = 0.f, Mth = -1e30f;
    float z0 = 0.f, z1 = 0.f;

    for (int it = 0; it < NTILES; ++it) {
        const uint32_t* Qcur = sh + ((it & 1) ? Q1_OFF : Q0_OFF);
        const uint32_t* Qold = sh + ((it & 1) ? Q0_OFF : Q1_OFF);   // tile it-1
        uint32_t*       Qnxt = sh + ((it & 1) ? Q0_OFF : Q1_OFF);   // tile it+1 (same buf)

        // mask for this tile
        int mreg = 0;
        if (tid < TT) mreg = mqb[it * TT + tid];

        // LDG prefetch of tile it+1 (consumed by STS after BAR1)
        bool has_next = (it + 1 < NTILES);
        float4 pf[8];
        if (has_next) {
            const float4* src = qb4 + (size_t)(it + 1) * TT * 64;
#pragma unroll
            for (int j = 0; j < 8; ++j) pf[j] = src[tid + j * NTHR];
        }

        // ---- kc loop: MMA tile it + z-update tile it-1 (1 token per kc)
        float c[8][4];
#pragma unroll
        for (int q = 0; q < 8; ++q) { c[q][0] = c[q][1] = c[q][2] = c[q][3] = 0.f; }

#pragma unroll 4
        for (int kc = 0; kc < 16; ++kc) {
            uint32_t a[2][4];
#pragma unroll
            for (int mt = 0; mt < 2; ++mt) {
                int arow = warp_m * 32 + mt * 16 + (lane & 15);
                int acol = kc * 8 + ((lane & 16) ? 4 : 0);
                uint32_t aaddr = (uint32_t)__cvta_generic_to_shared(&Qcur[arow * QSTR + acol]);
                asm volatile("ldmatrix.sync.aligned.m8n8.x4.shared.b16 {%0,%1,%2,%3}, [%4];"
                             : "=r"(a[mt][0]), "=r"(a[mt][1]), "=r"(a[mt][2]), "=r"(a[mt][3])
                             : "r"(aaddr));
            }
            // pipelined z for tile it-1: this thread's token for this kc step
            if (it) {
                int t = zq * 16 + kc;
                uint32_t qw = Qold[t * QSTR + zword];
                __nv_bfloat162 h2 = *reinterpret_cast<__nv_bfloat162*>(&qw);
                float e = e_sh[t];
                z0 += e * __bfloat162float(__low2bfloat16(h2));
                z1 += e * __bfloat162float(__high2bfloat16(h2));
            }
#pragma unroll
            for (int np = 0; np < 2; ++np) {
                int row   = warp_n * 32 + np * 16 + (lane & 7) + ((lane & 16) ? 8 : 0);
                int physB = (kc * 2 + ((lane & 8) ? 1 : 0)) ^ (row & 7);
                uint32_t baddr = (uint32_t)__cvta_generic_to_shared(&Wsh[row * 128 + physB * 4]);
                uint32_t b0, b1, b2, b3;
                asm volatile("ldmatrix.sync.aligned.m8n8.x4.shared.b16 {%0,%1,%2,%3}, [%4];"
                             : "=r"(b0), "=r"(b1), "=r"(b2), "=r"(b3) : "r"(baddr));
#pragma unroll
                for (int mt = 0; mt < 2; ++mt) {
                    float* c0 = c[mt * 4 + np * 2];
                    float* c1 = c[mt * 4 + np * 2 + 1];
                    asm volatile(
                        "mma.sync.aligned.m16n8k16.row.col.f32.bf16.bf16.f32 "
                        "{%0,%1,%2,%3}, {%4,%5,%6,%7}, {%8,%9}, {%0,%1,%2,%3};"
                        : "+f"(c0[0]), "+f"(c0[1]), "+f"(c0[2]), "+f"(c0[3])
                        : "r"(a[mt][0]), "r"(a[mt][1]), "r"(a[mt][2]), "r"(a[mt][3]),
                          "r"(b0), "r"(b1));
                    asm volatile(
                        "mma.sync.aligned.m16n8k16.row.col.f32.bf16.bf16.f32 "
                        "{%0,%1,%2,%3}, {%4,%5,%6,%7}, {%8,%9}, {%0,%1,%2,%3};"
                        : "+f"(c1[0]), "+f"(c1[1]), "+f"(c1[2]), "+f"(c1[3])
                        : "r"(a[mt][0]), "r"(a[mt][1]), "r"(a[mt][2]), "r"(a[mt][3]),
                          "r"(b2), "r"(b3));
                }
            }
        }
        __syncthreads();   // BAR1: z(it-1) reads done -> Qnxt writable; c regs complete

        // ---- STS tile it+1 (smem) overlapped with tanh epilogue (MUFU)
        if (has_next) {
#pragma unroll
            for (int j = 0; j < 8; ++j) {
                int idx = tid + j * NTHR;
                int row = idx >> 6, c4 = idx & 63;
                __nv_bfloat162 h0 = __floats2bfloat162_rn(pf[j].x, pf[j].y);
                __nv_bfloat162 h1 = __floats2bfloat162_rn(pf[j].z, pf[j].w);
                *reinterpret_cast<uint2*>(&Qnxt[row * QSTR + c4 * 2]) =
                    make_uint2(*reinterpret_cast<uint32_t*>(&h0),
                               *reinterpret_cast<uint32_t*>(&h1));
            }
        }

#pragma unroll
        for (int mt = 0; mt < 2; ++mt) {
            float p0 = 0.f, p1 = 0.f;
#pragma unroll
            for (int np = 0; np < 2; ++np) {
#pragma unroll
                for (int j = 0; j < 2; ++j) {
                    int n = warp_n * 32 + np * 16 + j * 8 + (lane & 3) * 2;
                    float4 wg = *reinterpret_cast<const float4*>(&wg_sh[n]);
                    float* cc = c[mt * 4 + np * 2 + j];
                    p0 += wg.x * fast_tanh(cc[0] + wg.y) + wg.z * fast_tanh(cc[1] + wg.w);
                    p1 += wg.x * fast_tanh(cc[2] + wg.y) + wg.z * fast_tanh(cc[3] + wg.w);
                }
            }
            p0 += __shfl_xor_sync(0xffffffffu, p0, 1);
            p0 += __shfl_xor_sync(0xffffffffu, p0, 2);
            p1 += __shfl_xor_sync(0xffffffffu, p1, 1);
            p1 += __shfl_xor_sync(0xffffffffu, p1, 2);
            if ((lane & 3) == 0) {
                int row0 = warp_m * 32 + mt * 16 + (lane >> 2);
                ap_sh[row0 * 8 + warp_n]       = p0;
                ap_sh[(row0 + 8) * 8 + warp_n] = p1;
            }
        }
        __syncthreads();   // BAR2: ap ready, STS done

        // ---- stage 1 (tid<64): e = exp(x-15)*m into e_sh for NEXT iteration's z
        if (tid < TT) {
            const float* ap = &ap_sh[tid * 8];
            float raw = ((ap[0] + ap[1]) + (ap[2] + ap[3])) +
                        ((ap[4] + ap[5]) + (ap[6] + ap[7])) + mb;
            float mflt = (float)mreg;
            float x = fminf(fmaxf(raw, -15.f), 15.f) * mflt;
            float e = __expf(x - 15.f) * mflt;
            e_sh[tid] = e;
            Sth += e;
            Mth = fmaxf(Mth, x);
        }
        __syncthreads();   // BAR3: e_sh ready
    }

    // ---- drain: z for last tile
    {
        const uint32_t* Qold = sh + (((NTILES - 1) & 1) ? Q1_OFF : Q0_OFF);
#pragma unroll
        for (int k = 0; k < 16; ++k) {
            int t = zq * 16 + k;
            uint32_t qw = Qold[t * QSTR + zword];
            __nv_bfloat162 h2 = *reinterpret_cast<__nv_bfloat162*>(&qw);
            float e = e_sh[t];
            z0 += e * __bfloat162float(__low2bfloat16(h2));
            z1 += e * __bfloat162float(__high2bfloat16(h2));
        }
    }
    __syncthreads();   // ph/zbuf reuse safe

    // ---- final reductions
    if (tid < TT) {
        float s = Sth, m = Mth;
#pragma unroll
        for (int o = 16; o; o >>= 1) {
            s += __shfl_xor_sync(0xffffffffu, s, o);
            m = fmaxf(m, __shfl_xor_sync(0xffffffffu, m, o));
        }
        if (lane == 0) { red[wid * 2] = s; red[wid * 2 + 1] = m; }
    }
    zbuf[zq * 256 + zword * 2]     = z0;
    zbuf[zq * 256 + zword * 2 + 1] = z1;
    __syncthreads();

    if (tid < 256) {
        float Sp = red[0] + red[2];
        float Mg = fmaxf(red[1], red[3]);
        float denom = Sp + 1e-6f * __expf(Mg - 15.f);
        float zt = (zbuf[tid] + zbuf[256 + tid]) + (zbuf[512 + tid] + zbuf[768 + tid]);
        out[b * 512 + tid]       = input_p[b * 256 + tid];
        out[b * 512 + 256 + tid] = zt / denom;
    }
}

extern "C" void kernel_launch(void* const* d_in, const int* in_sizes, int n_in,
                              void* d_out, int out_size) {
    const float* input_p = (const float*)d_in[0];
    const float* input_q = (const float*)d_in[2];
    const int*   mask_q  = (const int*)d_in[3];
    const float* h_tm1   = (const float*)d_in[4];
    const float* W_p_r   = (const float*)d_in[5];
    const float* b_p_r   = (const float*)d_in[6];
    const float* W_q     = (const float*)d_in[7];
    const float* b_q     = (const float*)d_in[8];
    const float* wv      = (const float*)d_in[9];
    const float* match_b = (const float*)d_in[10];
    float* out = (float*)d_out;

    size_t smemF = (size_t)SMEM_WORDS * 4;
    cudaFuncSetAttribute(kFused, cudaFuncAttributeMaxDynamicSharedMemorySize, (int)smemF);
    kFused<<<B_, NTHR, smemF>>>(input_q, W_q, wv, match_b, mask_q,
                                input_p, h_tm1, W_p_r, b_p_r, b_q, out);
}

// round 10
// speedup vs baseline: 1.2134x; 1.0151x over previous
#include <cuda_runtime.h>
#include <cuda_bf16.h>
#include <cstdint>

#define B_ 128
#define T_ 2048
#define TT 64
#define NTILES 32
#define NTHR 512

// smem word offsets
#define WSH_OFF 0            // 32768: W bf16, 128 words/row, XOR swizzle
#define Q0_OFF  32768        // 8192: Q tile, packed 128 words/row, XOR swizzle
#define Q1_OFF  40960        // 8192
#define WG_OFF  49152        // 512: float2 {w[d], gpr[d]}
#define E_OFF   49664        // 64
#define AP_OFF  49728        // 512: ap[64][8]
#define RED_OFF 50240        // 8
#define ZB_OFF  50248        // 1024: zbuf[4][256] (ph[512] in prologue)
#define SMEM_WORDS 51272

__device__ __forceinline__ float fast_tanh(float x) {
    float y;
    asm("tanh.approx.f32 %0, %1;" : "=f"(y) : "f"(x));
    return y;
}

__global__ __launch_bounds__(NTHR, 1)
void kFused(const float* __restrict__ input_q,
            const float* __restrict__ W_q,
            const float* __restrict__ wvec,
            const float* __restrict__ match_b,
            const int* __restrict__ mask_q,
            const float* __restrict__ input_p,
            const float* __restrict__ h_tm1,
            const float* __restrict__ W_p_r,
            const float* __restrict__ b_p_r,
            const float* __restrict__ b_q,
            float* __restrict__ out) {
    extern __shared__ uint32_t sh[];
    uint32_t* Wsh = sh + WSH_OFF;
    float2* wg_sh = reinterpret_cast<float2*>(sh + WG_OFF);
    float*  e_sh  = reinterpret_cast<float*>(sh + E_OFF);
    float*  ap_sh = reinterpret_cast<float*>(sh + AP_OFF);
    float*  red   = reinterpret_cast<float*>(sh + RED_OFF);
    float*  zbuf  = reinterpret_cast<float*>(sh + ZB_OFF);

    int b    = blockIdx.x;
    int tid  = threadIdx.x;
    int lane = tid & 31, wid = tid >> 5;

    // ================= Prologue =================
    float* ph = zbuf;                       // [512] = [input_p | h_tm1]
    if (tid < 256) ph[tid] = input_p[b * 256 + tid];
    else           ph[tid] = h_tm1[b * 256 + (tid - 256)];
    __syncthreads();

    // gpr: 16 warps x 16 rows (warp-coalesced dot)
    for (int r = 0; r < 16; ++r) {
        int d = wid * 16 + r;
        const float4* row = reinterpret_cast<const float4*>(W_p_r + (size_t)d * 512);
        const float4* p4  = reinterpret_cast<const float4*>(ph);
        float acc = 0.f;
#pragma unroll
        for (int i = 0; i < 4; ++i) {
            float4 wv = row[i * 32 + lane];
            float4 pv = p4[i * 32 + lane];
            acc += wv.x * pv.x + wv.y * pv.y + wv.z * pv.z + wv.w * pv.w;
        }
#pragma unroll
        for (int o = 16; o; o >>= 1) acc += __shfl_xor_sync(0xffffffffu, acc, o);
        if (lane == 0) wg_sh[d] = make_float2(wvec[d], acc + b_p_r[d] + b_q[d]);
    }

    // W_q -> bf16 smem, XOR swizzle
    for (int i = tid; i < 256 * 128; i += NTHR) {
        int n = i >> 7, kw = i & 127;
        float2 f = reinterpret_cast<const float2*>(W_q)[n * 128 + kw];
        __nv_bfloat162 h = __floats2bfloat162_rn(f.x, f.y);
        int phys = (kw >> 2) ^ (n & 7);
        Wsh[n * 128 + phys * 4 + (kw & 3)] = *reinterpret_cast<uint32_t*>(&h);
    }

    const float   mb  = match_b[0];
    const float4* qb4 = reinterpret_cast<const float4*>(input_q + (size_t)b * T_ * 256);
    const int*    mqb = mask_q + (size_t)b * T_;

    // Q tile 0 -> Qsh0 (packed 128 words/row, XOR swizzle)
#pragma unroll
    for (int j = 0; j < 8; ++j) {
        int idx = tid + j * NTHR;
        float4 f = qb4[idx];
        int row = idx >> 6, c4 = idx & 63;
        __nv_bfloat162 h0 = __floats2bfloat162_rn(f.x, f.y);
        __nv_bfloat162 h1 = __floats2bfloat162_rn(f.z, f.w);
        uint32_t phys = (uint32_t)(c4 >> 1) ^ (uint32_t)(row & 7);
        *reinterpret_cast<uint2*>(&sh[Q0_OFF + row * 128 + phys * 4 + (c4 & 1) * 2]) =
            make_uint2(*reinterpret_cast<uint32_t*>(&h0), *reinterpret_cast<uint32_t*>(&h1));
    }
    __syncthreads();

    // ================= Main loop =================
    int warp_m = wid & 1;       // 2 warps over 64 tokens (m32)
    int warp_n = wid >> 1;      // 8 warps over 256 douts (n32)
    int zword = tid & 127;      // d-pair word
    int zq    = tid >> 7;       // t-quarter (16 tokens)
    int zc    = zword >> 2, zr = zword & 3;

    float Sth = 0.f, Mth = -1e30f;
    float z0 = 0.f, z1 = 0.f;

    for (int it = 0; it < NTILES; ++it) {
        const uint32_t Qcur_off = (it & 1) ? Q1_OFF : Q0_OFF;
        const uint32_t Qnxt_off = (it & 1) ? Q0_OFF : Q1_OFF;

        int mreg = 0;
        if (tid < TT) mreg = mqb[it * TT + tid];

        bool has_next = (it + 1 < NTILES);
        const float4* src = qb4 + (size_t)(it + 1) * TT * 64;

        // ---- kc loop: MMA + chunked staging (LDG at even kc, STS at odd kc)
        float c[8][4];
#pragma unroll
        for (int q = 0; q < 8; ++q) { c[q][0] = c[q][1] = c[q][2] = c[q][3] = 0.f; }

        float4 stg;
#pragma unroll
        for (int kc = 0; kc < 16; ++kc) {
            uint32_t a[2][4];
#pragma unroll
            for (int mt = 0; mt < 2; ++mt) {
                int arow  = warp_m * 32 + mt * 16 + (lane & 15);
                int physA = (kc * 2 + ((lane & 16) ? 1 : 0)) ^ (arow & 7);
                uint32_t aaddr = (uint32_t)__cvta_generic_to_shared(
                    &sh[Qcur_off + arow * 128 + physA * 4]);
                asm volatile("ldmatrix.sync.aligned.m8n8.x4.shared.b16 {%0,%1,%2,%3}, [%4];"
                             : "=r"(a[mt][0]), "=r"(a[mt][1]), "=r"(a[mt][2]), "=r"(a[mt][3])
                             : "r"(aaddr));
            }

            // staging: one float4 per thread per 2 kc steps
            if (has_next) {
                if ((kc & 1) == 0) {
                    stg = src[tid + (kc >> 1) * NTHR];
                } else {
                    int idx = tid + (kc >> 1) * NTHR;
                    int row = idx >> 6, c4 = idx & 63;
                    __nv_bfloat162 h0 = __floats2bfloat162_rn(stg.x, stg.y);
                    __nv_bfloat162 h1 = __floats2bfloat162_rn(stg.z, stg.w);
                    uint32_t phys = (uint32_t)(c4 >> 1) ^ (uint32_t)(row & 7);
                    *reinterpret_cast<uint2*>(&sh[Qnxt_off + row * 128 + phys * 4 + (c4 & 1) * 2]) =
                        make_uint2(*reinterpret_cast<uint32_t*>(&h0),
                                   *reinterpret_cast<uint32_t*>(&h1));
                }
            }

#pragma unroll
            for (int np = 0; np < 2; ++np) {
                int row   = warp_n * 32 + np * 16 + (lane & 7) + ((lane & 16) ? 8 : 0);
                int physB = (kc * 2 + ((lane & 8) ? 1 : 0)) ^ (row & 7);
                uint32_t baddr = (uint32_t)__cvta_generic_to_shared(&Wsh[row * 128 + physB * 4]);
                uint32_t b0, b1, b2, b3;
                asm volatile("ldmatrix.sync.aligned.m8n8.x4.shared.b16 {%0,%1,%2,%3}, [%4];"
                             : "=r"(b0), "=r"(b1), "=r"(b2), "=r"(b3) : "r"(baddr));
#pragma unroll
                for (int mt = 0; mt < 2; ++mt) {
                    float* c0 = c[mt * 4 + np * 2];
                    float* c1 = c[mt * 4 + np * 2 + 1];
                    asm volatile(
                        "mma.sync.aligned.m16n8k16.row.col.f32.bf16.bf16.f32 "
                        "{%0,%1,%2,%3}, {%4,%5,%6,%7}, {%8,%9}, {%0,%1,%2,%3};"
                        : "+f"(c0[0]), "+f"(c0[1]), "+f"(c0[2]), "+f"(c0[3])
                        : "r"(a[mt][0]), "r"(a[mt][1]), "r"(a[mt][2]), "r"(a[mt][3]),
                          "r"(b0), "r"(b1));
                    asm volatile(
                        "mma.sync.aligned.m16n8k16.row.col.f32.bf16.bf16.f32 "
                        "{%0,%1,%2,%3}, {%4,%5,%6,%7}, {%8,%9}, {%0,%1,%2,%3};"
                        : "+f"(c1[0]), "+f"(c1[1]), "+f"(c1[2]), "+f"(c1[3])
                        : "r"(a[mt][0]), "r"(a[mt][1]), "r"(a[mt][2]), "r"(a[mt][3]),
                          "r"(b2), "r"(b3));
                }
            }
        }

        // ---- epilogue: tanh + dot(w), quad reduce, disjoint partial writes
#pragma unroll
        for (int mt = 0; mt < 2; ++mt) {
            float p0 = 0.f, p1 = 0.f;
#pragma unroll
            for (int np = 0; np < 2; ++np) {
#pragma unroll
                for (int j = 0; j < 2; ++j) {
                    int n = warp_n * 32 + np * 16 + j * 8 + (lane & 3) * 2;
                    float4 wg = *reinterpret_cast<const float4*>(&wg_sh[n]);
                    float* cc = c[mt * 4 + np * 2 + j];
                    p0 += wg.x * fast_tanh(cc[0] + wg.y) + wg.z * fast_tanh(cc[1] + wg.w);
                    p1 += wg.x * fast_tanh(cc[2] + wg.y) + wg.z * fast_tanh(cc[3] + wg.w);
                }
            }
            p0 += __shfl_xor_sync(0xffffffffu, p0, 1);
            p0 += __shfl_xor_sync(0xffffffffu, p0, 2);
            p1 += __shfl_xor_sync(0xffffffffu, p1, 1);
            p1 += __shfl_xor_sync(0xffffffffu, p1, 2);
            if ((lane & 3) == 0) {
                int row0 = warp_m * 32 + mt * 16 + (lane >> 2);
                ap_sh[row0 * 8 + warp_n]       = p0;
                ap_sh[(row0 + 8) * 8 + warp_n] = p1;
            }
        }
        __syncthreads();   // S1: ap ready, STS(Qnxt) done

        // ---- stage 1 (tid<64): e = exp(x-15)*m
        if (tid < TT) {
            const float* ap = &ap_sh[tid * 8];
            float raw = ((ap[0] + ap[1]) + (ap[2] + ap[3])) +
                        ((ap[4] + ap[5]) + (ap[6] + ap[7])) + mb;
            float mflt = (float)mreg;
            float x = fminf(fmaxf(raw, -15.f), 15.f) * mflt;
            float e = __expf(x - 15.f) * mflt;
            e_sh[tid] = e;
            Sth += e;
            Mth = fmaxf(Mth, x);
        }
        __syncthreads();   // S2: e_sh ready

        // ---- z update: thread owns d-pair zword, t-quarter zq (16 tokens)
        {
            float a0 = 0.f, a1 = 0.f;
            int tb = zq * 16;
#pragma unroll
            for (int k = 0; k < 16; ++k) {
                int t = tb + k;
                uint32_t qw = sh[Qcur_off + t * 128 + (((uint32_t)zc ^ (uint32_t)(t & 7)) << 2) + zr];
                __nv_bfloat162 h2 = *reinterpret_cast<__nv_bfloat162*>(&qw);
                float e = e_sh[t];
                a0 += e * __bfloat162float(__low2bfloat16(h2));
                a1 += e * __bfloat162float(__high2bfloat16(h2));
            }
            z0 += a0;
            z1 += a1;
        }
        __syncthreads();   // S3: Qcur reads done (next iter's STS may overwrite it)
    }

    // ================= Final =================
    if (tid < TT) {
        float s = Sth, m = Mth;
#pragma unroll
        for (int o = 16; o; o >>= 1) {
            s += __shfl_xor_sync(0xffffffffu, s, o);
            m = fmaxf(m, __shfl_xor_sync(0xffffffffu, m, o));
        }
        if (lane == 0) { red[wid * 2] = s; red[wid * 2 + 1] = m; }
    }
    __syncthreads();       // zbuf (aliases ph) now safe to reuse
    zbuf[zq * 256 + zword * 2]     = z0;
    zbuf[zq * 256 + zword * 2 + 1] = z1;
    __syncthreads();

    if (tid < 256) {
        float Sp = red[0] + red[2];
        float Mg = fmaxf(red[1], red[3]);
        float denom = Sp + 1e-6f * __expf(Mg - 15.f);
        float zt = (zbuf[tid] + zbuf[256 + tid]) + (zbuf[512 + tid] + zbuf[768 + tid]);
        out[b * 512 + tid]       = input_p[b * 256 + tid];
        out[b * 512 + 256 + tid] = zt / denom;
    }
}

extern "C" void kernel_launch(void* const* d_in, const int* in_sizes, int n_in,
                              void* d_out, int out_size) {
    const float* input_p = (const float*)d_in[0];
    const float* input_q = (const float*)d_in[2];
    const int*   mask_q  = (const int*)d_in[3];
    const float* h_tm1   = (const float*)d_in[4];
    const float* W_p_r   = (const float*)d_in[5];
    const float* b_p_r   = (const float*)d_in[6];
    const float* W_q     = (const float*)d_in[7];
    const float* b_q     = (const float*)d_in[8];
    const float* wv      = (const float*)d_in[9];
    const float* match_b = (const float*)d_in[10];
    float* out = (float*)d_out;

    size_t smemF = (size_t)SMEM_WORDS * 4;
    cudaFuncSetAttribute(kFused, cudaFuncAttributeMaxDynamicSharedMemorySize, (int)smemF);
    kFused<<<B_, NTHR, smemF>>>(input_q, W_q, wv, match_b, mask_q,
                                input_p, h_tm1, W_p_r, b_p_r, b_q, out);
}